// round 12
// baseline (speedup 1.0000x reference)
#include <cuda_runtime.h>
#include <cuda_fp16.h>
#include <cstdint>

#define CDIM 256
#define KCB  512

static const int N_ENC0  = 8*256*64*64;        // 8388608
static const int OFF_Z   = N_ENC0;
static const int OFF_STE = N_ENC0 + 8*2*64*64; // + 65536

// ---- scratch (device globals; no allocation anywhere) ----
__device__ float g_img1[8*3*128*128];
__device__ float g_img2[8*3*64*64];
__device__ float g_enc0[8*64*64*256];   // NHWC scale0 (fp32 for output region 0)
__device__ float g_cbsq[2*KCB];         // ||cb||^2, 1024 rows
// fp16 hi/lo split operands, k-PERMUTED within each 16-chunk:
// j=k&15 -> slot = ((j&7)>>1)*4 + ((j>>3)<<1) + (j&1)   (lane t4 owns slots 4t4..4t4+3)
__device__ __half g_ehi[43008*256];     // concat enc0|enc1|enc2 rows
__device__ __half g_elo[43008*256];
__device__ __half g_cbhi[1024*256];     // cb0 rows 0..511, cb1 rows 512..1023
__device__ __half g_cblo[1024*256];
// per-(quarter, position) partials: cb0: q*43008 + pos ; cb1: 172032 + q*32768 + pos
__device__ float g_hM[303104];
__device__ float g_hL[303104];
__device__ int   g_hI[303104];

// m16n8k16 fp16 MMA, fp32 accum (sm_80+ PTX)
__device__ __forceinline__ void mma_f16(float* c, uint2 a01, uint2 a23, uint2 b) {
    asm volatile("mma.sync.aligned.m16n8k16.row.col.f32.f16.f16.f32 "
        "{%0,%1,%2,%3}, {%4,%5,%6,%7}, {%8,%9}, {%0,%1,%2,%3};"
        : "+f"(c[0]), "+f"(c[1]), "+f"(c[2]), "+f"(c[3])
        : "r"(a01.x), "r"(a23.x), "r"(a01.y), "r"(a23.y),
          "r"(b.x),  "r"(b.y));
}

__device__ __forceinline__ int permcol(int k) {
    int j = k & 15;
    return (k & ~15) + ((j & 7) >> 1)*4 + ((j >> 3) << 1) + (j & 1);
}

// ======================= small kernels =======================
// merged bilinear downsample: blocks [0,1536) -> f=2 into g_img1; [1536,1920) -> f=4 into g_img2
__global__ void ds_kernel(const float* __restrict__ img)
{
    int sel = (blockIdx.x >= 1536);
    int base = sel ? 1536*256 : 0;
    int Wout = sel ? 64 : 128;
    int f    = sel ? 4 : 2;
    int o    = sel ? 1 : 0;
    float* out = sel ? g_img2 : g_img1;
    int idx = blockIdx.x*blockDim.x + threadIdx.x - base;
    int total = 8*3*Wout*Wout;
    if (idx >= total) return;
    int x = idx % Wout, y = (idx / Wout) % Wout, bc = idx / (Wout*Wout);
    const float* p = img + (size_t)bc*256*256;
    int ry = y*f + o, rx = x*f + o;
    out[idx] = 0.25f*(p[ry*256+rx] + p[ry*256+rx+1] + p[(ry+1)*256+rx] + p[(ry+1)*256+rx+1]);
}

// codebook: squared norms + fp16 hi/lo split (k-permuted). grid 1024, block 256.
__global__ void __launch_bounds__(256) cbprep_kernel(const float* __restrict__ cbs)
{
    __shared__ float red[8];
    int r = blockIdx.x, k = threadIdx.x;
    float v = cbs[(size_t)r*256 + k];
    __half h = __float2half_rn(v);
    __half l = __float2half_rn(v - __half2float(h));
    size_t o = (size_t)r*256 + permcol(k);
    g_cbhi[o] = h; g_cblo[o] = l;
    float s = v*v;
    #pragma unroll
    for (int off = 16; off > 0; off >>= 1) s += __shfl_xor_sync(0xffffffffu, s, off);
    if ((k & 31) == 0) red[k >> 5] = s;
    __syncthreads();
    if (k == 0) {
        float t = 0.f;
        #pragma unroll
        for (int i = 0; i < 8; i++) t += red[i];
        g_cbsq[r] = t;
    }
}

// stride-4 4x4 conv, 3 in-ch -> 256 out-ch; writes fp16 split (+ fp32 NHWC for scale0)
// grid: (Hout, B); block: 256 threads (one per out channel). 4 independent x-chains.
__global__ void __launch_bounds__(256) conv_kernel(
    const float* __restrict__ ext_img, const float* __restrict__ w,
    const float* __restrict__ bias, int which)
{
    __shared__ float ins[12][256];
    int o = threadIdx.x;
    int y = blockIdx.x, b = blockIdx.y;
    int Hout = gridDim.x;
    int Win  = Hout * 4;

    const float* img = (which == 0) ? ext_img : (which == 1 ? g_img1 : g_img2);
    int rowbase = (which == 0) ? (b*64 + y)*64
                : (which == 1) ? 32768 + (b*32 + y)*32
                               : 40960 + (b*16 + y)*16;

    int tot = 12*Win;
    for (int i = o; i < tot; i += 256) {
        int x = i % Win; int r = i / Win;
        ins[r][x] = img[(((size_t)b*3 + (r>>2))*Win + 4*y + (r&3))*Win + x];
    }
    float wreg[48];
    #pragma unroll
    for (int j = 0; j < 48; j++) wreg[j] = w[(size_t)o*48 + j];
    float bo = bias[o];
    __syncthreads();

    int oc = permcol(o);
    for (int x = 0; x < Hout; x += 4) {
        // four independent chains; per-x summation order j=0..47 unchanged
        float a0 = bo, a1 = bo, a2 = bo, a3 = bo;
        #pragma unroll
        for (int j = 0; j < 48; j++) {
            int ic = j >> 4, ky = (j >> 2) & 3, kx = j & 3;
            float wv = wreg[j];
            const float* row = &ins[ic*4+ky][0];
            a0 += wv * row[4*x + kx];
            a1 += wv * row[4*x + 4 + kx];
            a2 += wv * row[4*x + 8 + kx];
            a3 += wv * row[4*x + 12 + kx];
        }
        float av[4] = {a0, a1, a2, a3};
        #pragma unroll
        for (int t = 0; t < 4; t++) {
            size_t prow = (size_t)rowbase + x + t;
            if (which == 0) g_enc0[prow*256 + o] = av[t];
            __half h = __float2half_rn(av[t]);
            __half l = __float2half_rn(av[t] - __half2float(h));
            g_ehi[prow*256 + oc] = h;
            g_elo[prow*256 + oc] = l;
        }
    }
}

// NHWC -> NCHW transpose for enc0 into output region 0
__global__ void __launch_bounds__(256) transpose_kernel(float* __restrict__ out)
{
    __shared__ float t[32][33];
    int tid = threadIdx.x;
    int p0 = blockIdx.x * 32;
    int c0 = blockIdx.y * 32;
    #pragma unroll
    for (int it = 0; it < 4; it++) {
        int r = (tid >> 5) + it*8, cc = tid & 31;
        t[r][cc] = g_enc0[(size_t)(p0 + r)*256 + c0 + cc];
    }
    __syncthreads();
    #pragma unroll
    for (int it = 0; it < 4; it++) {
        int r = (tid >> 5) + it*8, pc = tid & 31;
        int gp = p0 + pc;
        int b = gp >> 12, p = gp & 4095;
        out[((size_t)b*256 + c0 + r)*4096 + p] = t[pc][r];
    }
}

// ======================= fp16 mma.sync distance =======================
// CTA: M=128 positions x N=128 codes (quarter codebook), K=256 in 8 chunks of 32.
// dot ~= Ahi*Bhi + Ahi*Blo + Alo*Bhi (products exact in fp32 accum; dropped lo*lo ~2^-22).
// 8 warps: wm=w&1 (M 64), wn=w>>1 (N 32). Warp tile 64x32, 3 x m16n8k16 per (mt,u).
#define STRH 48                         // compact: 96B stride, conflict-free compute loads
#define TILEH (128*STRH)                // 6144 halves = 12288 B per operand
#define DSMEM (4*TILEH*2 + 512)        // 49664 bytes -> 2 CTAs/SM

__global__ void __launch_bounds__(256, 2) dist_mma_kernel()
{
    extern __shared__ char smem[];
    __half* sAhi = (__half*)smem;
    __half* sAlo = sAhi + TILEH;
    __half* sBhi = sAlo + TILEH;
    __half* sBlo = sBhi + TILEH;
    float*  cbs_s = (float*)(smem + 4*TILEH*2);   // 128 floats

    int tid = threadIdx.x;
    int lane = tid & 31, w = tid >> 5;
    int g = lane >> 2, t4 = lane & 3;
    int wm = w & 1, wn = w >> 1;

    int blk = blockIdx.x;
    int seg, mtile, q;
    if (blk < 1344) { seg = 0; mtile = blk >> 2; q = blk & 3; }
    else            { seg = 1; mtile = (blk - 1344) >> 2; q = (blk - 1344) & 3; }

    const __half* Ahi_g = g_ehi + (size_t)mtile*128*256;
    const __half* Alo_g = g_elo + (size_t)mtile*128*256;
    int cbrow = (seg ? 512 : 0) + q*128;
    const __half* Bhi_g = g_cbhi + (size_t)cbrow*256;
    const __half* Blo_g = g_cblo + (size_t)cbrow*256;

    if (tid < 128) cbs_s[tid] = g_cbsq[cbrow + tid];

    float acc[4][4][4];
    #pragma unroll
    for (int mt = 0; mt < 4; mt++)
        #pragma unroll
        for (int u = 0; u < 4; u++)
            #pragma unroll
            for (int e = 0; e < 4; e++) acc[mt][u][e] = 0.f;

    const __half* gsrc[4] = {Ahi_g, Alo_g, Bhi_g, Blo_g};
    __half* sdst[4] = {sAhi, sAlo, sBhi, sBlo};

    for (int kc = 0; kc < 8; kc++) {
        if (kc > 0) __syncthreads();
        #pragma unroll
        for (int op = 0; op < 4; op++) {
            #pragma unroll
            for (int it = 0; it < 2; it++) {
                int c = it*256 + tid;
                int r = c >> 2, sgs = c & 3;
                *(uint4*)(sdst[op] + r*STRH + sgs*8) =
                    *(const uint4*)(gsrc[op] + (size_t)r*256 + kc*32 + sgs*8);
            }
        }
        __syncthreads();

        #pragma unroll
        for (int s = 0; s < 2; s++) {
            int ko = s*16 + t4*4;
            uint2 bhf[4], blf[4];
            #pragma unroll
            for (int u = 0; u < 4; u++) {
                int br = (wn*32 + u*8 + g)*STRH + ko;
                bhf[u] = *(uint2*)(sBhi + br);
                blf[u] = *(uint2*)(sBlo + br);
            }
            #pragma unroll
            for (int mt = 0; mt < 4; mt++) {
                int ar = (wm*64 + mt*16 + g)*STRH + ko;
                uint2 ah0 = *(uint2*)(sAhi + ar);
                uint2 ah1 = *(uint2*)(sAhi + ar + 8*STRH);
                uint2 al0 = *(uint2*)(sAlo + ar);
                uint2 al1 = *(uint2*)(sAlo + ar + 8*STRH);
                #pragma unroll
                for (int u = 0; u < 4; u++) {
                    mma_f16(acc[mt][u], ah0, ah1, bhf[u]);
                    mma_f16(acc[mt][u], ah0, ah1, blf[u]);
                    mma_f16(acc[mt][u], al0, al1, bhf[u]);
                }
            }
        }
    }
    __syncthreads();

    // partial overlay in smem (tiles dead now)
    float* Mp = (float*)smem;           // [128][4]
    float* Lp = Mp + 512;
    int*   Ip = (int*)(Mp + 1024);

    const float NEG = -3.402823466e38f;
    #pragma unroll
    for (int mt = 0; mt < 4; mt++) {
        #pragma unroll
        for (int half = 0; half < 2; half++) {
            int row = wm*64 + mt*16 + g + half*8;
            float M = NEG, L = 0.f; int I = 0;
            #pragma unroll
            for (int u = 0; u < 4; u++) {
                #pragma unroll
                for (int j = 0; j < 2; j++) {
                    int col = wn*32 + u*8 + 2*t4 + j;
                    float s = 2.f*acc[mt][u][half*2 + j] - cbs_s[col];
                    if (s > M) { L = L*expf(M - s) + 1.f; M = s; I = col; }
                    else       { L += expf(s - M); }
                }
            }
            #pragma unroll
            for (int off = 1; off <= 2; off <<= 1) {
                float m2 = __shfl_xor_sync(0xffffffffu, M, off);
                float l2 = __shfl_xor_sync(0xffffffffu, L, off);
                int   i2 = __shfl_xor_sync(0xffffffffu, I, off);
                float mn = fmaxf(M, m2);
                L = L*expf(M - mn) + l2*expf(m2 - mn);
                if (m2 > M || (m2 == M && i2 < I)) I = i2;
                M = mn;
            }
            if (t4 == 0) { Mp[row*4 + wn] = M; Lp[row*4 + wn] = L; Ip[row*4 + wn] = I; }
        }
    }
    __syncthreads();

    if (tid < 128) {
        float M = Mp[tid*4], L = Lp[tid*4]; int I = Ip[tid*4];
        #pragma unroll
        for (int n = 1; n < 4; n++) {
            float m2 = Mp[tid*4 + n], l2 = Lp[tid*4 + n];
            float mn = fmaxf(M, m2);
            L = L*expf(M - mn) + l2*expf(m2 - mn);
            if (m2 > M) I = Ip[tid*4 + n];   // ascending col blocks: ties keep first
            M = mn;
        }
        int pos = mtile*128 + tid;
        int slot = seg ? (172032 + q*32768 + pos) : (q*43008 + pos);
        g_hM[slot] = M; g_hL[slot] = L; g_hI[slot] = q*128 + I;
    }
}

// ======================= fuse =======================
__device__ __forceinline__ void merge4(int pos, int base, int stride, float& P, int& idx)
{
    float M = g_hM[base + pos], L = g_hL[base + pos]; int I = g_hI[base + pos];
    #pragma unroll
    for (int n = 1; n < 4; n++) {
        int s = base + n*stride + pos;
        float m2 = g_hM[s], l2 = g_hL[s];
        float mn = fmaxf(M, m2);
        L = L*expf(M - mn) + l2*expf(m2 - mn);
        if (m2 > M) I = g_hI[s];     // ascending quarters: ties keep first
        M = mn;
    }
    P = 1.f / L; idx = I;
}

__global__ void __launch_bounds__(256) fuse_kernel(
    const float* __restrict__ cbs, float* __restrict__ out)
{
    const float* cb0 = cbs;
    const float* cb1 = cbs + (size_t)KCB*CDIM;
    int x = threadIdx.x & 63;
    int y = blockIdx.x*4 + (threadIdx.x >> 6);
    int b = blockIdx.y;
    int pos0 = (b*64 + y)*64 + x;
    int pos1 = 32768 + (b*32 + (y>>1))*32 + (x>>1);
    int pos2 = 40960 + (b*16 + (y>>2))*16 + (x>>2);

    float pA, pB, pC; int zA, zB, zC;
    merge4(pos0, 0, 43008, pA, zA);
    merge4(pos1, 0, 43008, pB, zB);
    merge4(pos2, 0, 43008, pC, zC);
    int z1 = zA; float best = pA;
    if (pB > best) { best = pB; z1 = zB; }
    if (pC > best) { best = pC; z1 = zC; }
    float p2d; int z2;
    merge4(pos0, 172032, 32768, p2d, z2);

    out[OFF_Z + ((size_t)(b*2+0)*64 + y)*64 + x] = (float)z1;
    out[OFF_Z + ((size_t)(b*2+1)*64 + y)*64 + x] = (float)z2;

    const float4* r0 = (const float4*)(cb0 + (size_t)z1*CDIM);
    const float4* r1 = (const float4*)(cb1 + (size_t)z2*CDIM);
    size_t obase = (size_t)OFF_STE + (size_t)b*256*4096 + (size_t)y*64 + x;
    for (int c4 = 0; c4 < 64; c4++) {
        float4 a = r0[c4], qv = r1[c4];
        int c = c4*4;
        out[obase + (size_t)(c+0)*4096] = 0.5f*(a.x + qv.x);
        out[obase + (size_t)(c+1)*4096] = 0.5f*(a.y + qv.y);
        out[obase + (size_t)(c+2)*4096] = 0.5f*(a.z + qv.z);
        out[obase + (size_t)(c+3)*4096] = 0.5f*(a.w + qv.w);
    }
}

// ======================= launch =======================
extern "C" void kernel_launch(void* const* d_in, const int* in_sizes, int n_in,
                              void* d_out, int out_size)
{
    const float* image     = (const float*)d_in[0];  // (8,3,256,256)
    const float* conv_w    = (const float*)d_in[1];  // (256,3,4,4)
    const float* conv_b    = (const float*)d_in[2];  // (256,)
    const float* codebooks = (const float*)d_in[3];  // (4,512,256)
    float* out = (float*)d_out;

    cudaFuncSetAttribute(dist_mma_kernel, cudaFuncAttributeMaxDynamicSharedMemorySize, DSMEM);

    ds_kernel<<<1920, 256>>>(image);
    cbprep_kernel<<<1024, 256>>>(codebooks);

    conv_kernel<<<dim3(64, 8), 256>>>(image, conv_w, conv_b, 0);
    conv_kernel<<<dim3(32, 8), 256>>>(image, conv_w, conv_b, 1);
    conv_kernel<<<dim3(16, 8), 256>>>(image, conv_w, conv_b, 2);

    transpose_kernel<<<dim3(1024, 8), 256>>>(out);

    // cb0: 336 mtiles x 4 quarters = 1344 ; cb1: 256 x 4 = 1024
    dist_mma_kernel<<<2368, 256, DSMEM>>>();

    fuse_kernel<<<dim3(16, 8), 256>>>(codebooks, out);
}

// round 13
// speedup vs baseline: 1.5439x; 1.5439x over previous
#include <cuda_runtime.h>
#include <cuda_fp16.h>
#include <cstdint>

#define CDIM 256
#define KCB  512

static const int N_ENC0  = 8*256*64*64;        // 8388608
static const int OFF_Z   = N_ENC0;
static const int OFF_STE = N_ENC0 + 8*2*64*64; // + 65536

// ---- scratch (device globals; no allocation anywhere) ----
__device__ float g_img1[8*3*128*128];
__device__ float g_img2[8*3*64*64];
__device__ float g_enc0[8*64*64*256];   // NHWC scale0 (fp32 for output region 0)
__device__ float g_cbsq[2*KCB];         // ||cb||^2, 1024 rows
// fp16 hi/lo split operands, k-PERMUTED within each 16-chunk:
// j=k&15 -> slot = ((j&7)>>1)*4 + ((j>>3)<<1) + (j&1)   (lane t4 owns slots 4t4..4t4+3)
__device__ __half g_ehi[43008*256];     // concat enc0|enc1|enc2 rows
__device__ __half g_elo[43008*256];
__device__ __half g_cbhi[1024*256];     // cb0 rows 0..511, cb1 rows 512..1023
__device__ __half g_cblo[1024*256];
// per-(quarter, position) partials: cb0: q*43008 + pos ; cb1: 172032 + q*32768 + pos
__device__ float g_hM[303104];
__device__ float g_hL[303104];
__device__ int   g_hI[303104];

// m16n8k16 fp16 MMA, fp32 accum (sm_80+ PTX)
__device__ __forceinline__ void mma_f16(float* c, uint2 a01, uint2 a23, uint2 b) {
    asm volatile("mma.sync.aligned.m16n8k16.row.col.f32.f16.f16.f32 "
        "{%0,%1,%2,%3}, {%4,%5,%6,%7}, {%8,%9}, {%0,%1,%2,%3};"
        : "+f"(c[0]), "+f"(c[1]), "+f"(c[2]), "+f"(c[3])
        : "r"(a01.x), "r"(a23.x), "r"(a01.y), "r"(a23.y),
          "r"(b.x),  "r"(b.y));
}

__device__ __forceinline__ int permcol(int k) {
    int j = k & 15;
    return (k & ~15) + ((j & 7) >> 1)*4 + ((j >> 3) << 1) + (j & 1);
}

// ======================= small kernels =======================
// merged bilinear downsample: blocks [0,1536) -> f=2 into g_img1; [1536,1920) -> f=4 into g_img2
__global__ void ds_kernel(const float* __restrict__ img)
{
    int sel = (blockIdx.x >= 1536);
    int base = sel ? 1536*256 : 0;
    int Wout = sel ? 64 : 128;
    int f    = sel ? 4 : 2;
    int o    = sel ? 1 : 0;
    float* out = sel ? g_img2 : g_img1;
    int idx = blockIdx.x*blockDim.x + threadIdx.x - base;
    int total = 8*3*Wout*Wout;
    if (idx >= total) return;
    int x = idx % Wout, y = (idx / Wout) % Wout, bc = idx / (Wout*Wout);
    const float* p = img + (size_t)bc*256*256;
    int ry = y*f + o, rx = x*f + o;
    out[idx] = 0.25f*(p[ry*256+rx] + p[ry*256+rx+1] + p[(ry+1)*256+rx] + p[(ry+1)*256+rx+1]);
}

// codebook: squared norms + fp16 hi/lo split (k-permuted). grid 1024, block 256.
__global__ void __launch_bounds__(256) cbprep_kernel(const float* __restrict__ cbs)
{
    __shared__ float red[8];
    int r = blockIdx.x, k = threadIdx.x;
    float v = cbs[(size_t)r*256 + k];
    __half h = __float2half_rn(v);
    __half l = __float2half_rn(v - __half2float(h));
    size_t o = (size_t)r*256 + permcol(k);
    g_cbhi[o] = h; g_cblo[o] = l;
    float s = v*v;
    #pragma unroll
    for (int off = 16; off > 0; off >>= 1) s += __shfl_xor_sync(0xffffffffu, s, off);
    if ((k & 31) == 0) red[k >> 5] = s;
    __syncthreads();
    if (k == 0) {
        float t = 0.f;
        #pragma unroll
        for (int i = 0; i < 8; i++) t += red[i];
        g_cbsq[r] = t;
    }
}

// stride-4 4x4 conv, 3 in-ch -> 256 out-ch; writes fp16 split (+ fp32 NHWC for scale0)
// grid: (Hout, B); block: 256 threads (one per out channel).
// 2 independent x-chains; LDS.128 loads (kx taps contiguous); j-order preserved exactly.
__global__ void __launch_bounds__(256) conv_kernel(
    const float* __restrict__ ext_img, const float* __restrict__ w,
    const float* __restrict__ bias, int which)
{
    __shared__ __align__(16) float ins[12][256];
    int o = threadIdx.x;
    int y = blockIdx.x, b = blockIdx.y;
    int Hout = gridDim.x;
    int Win  = Hout * 4;

    const float* img = (which == 0) ? ext_img : (which == 1 ? g_img1 : g_img2);
    int rowbase = (which == 0) ? (b*64 + y)*64
                : (which == 1) ? 32768 + (b*32 + y)*32
                               : 40960 + (b*16 + y)*16;

    int tot = 12*Win;
    for (int i = o; i < tot; i += 256) {
        int x = i % Win; int r = i / Win;      // r = ic*4 + ky
        ins[r][x] = img[(((size_t)b*3 + (r>>2))*Win + 4*y + (r&3))*Win + x];
    }
    float wreg[48];
    #pragma unroll
    for (int j = 0; j < 48; j++) wreg[j] = w[(size_t)o*48 + j];
    float bo = bias[o];
    __syncthreads();

    int oc = permcol(o);
    for (int x = 0; x < Hout; x += 2) {
        float aA = bo, aB = bo;
        #pragma unroll
        for (int r = 0; r < 12; r++) {
            // j = r*4 + kx; kx fastest -> identical summation order to scalar loop
            float4 vA = *(const float4*)&ins[r][4*x];
            float4 vB = *(const float4*)&ins[r][4*x + 4];
            aA += wreg[r*4+0]*vA.x; aB += wreg[r*4+0]*vB.x;
            aA += wreg[r*4+1]*vA.y; aB += wreg[r*4+1]*vB.y;
            aA += wreg[r*4+2]*vA.z; aB += wreg[r*4+2]*vB.z;
            aA += wreg[r*4+3]*vA.w; aB += wreg[r*4+3]*vB.w;
        }
        size_t pA = (size_t)rowbase + x, pB = pA + 1;
        if (which == 0) {
            g_enc0[pA*256 + o] = aA;
            g_enc0[pB*256 + o] = aB;
        }
        __half hA = __float2half_rn(aA);
        __half lA = __float2half_rn(aA - __half2float(hA));
        __half hB = __float2half_rn(aB);
        __half lB = __float2half_rn(aB - __half2float(hB));
        g_ehi[pA*256 + oc] = hA; g_elo[pA*256 + oc] = lA;
        g_ehi[pB*256 + oc] = hB; g_elo[pB*256 + oc] = lB;
    }
}

// NHWC -> NCHW transpose for enc0 into output region 0
__global__ void __launch_bounds__(256) transpose_kernel(float* __restrict__ out)
{
    __shared__ float t[32][33];
    int tid = threadIdx.x;
    int p0 = blockIdx.x * 32;
    int c0 = blockIdx.y * 32;
    #pragma unroll
    for (int it = 0; it < 4; it++) {
        int r = (tid >> 5) + it*8, cc = tid & 31;
        t[r][cc] = g_enc0[(size_t)(p0 + r)*256 + c0 + cc];
    }
    __syncthreads();
    #pragma unroll
    for (int it = 0; it < 4; it++) {
        int r = (tid >> 5) + it*8, pc = tid & 31;
        int gp = p0 + pc;
        int b = gp >> 12, p = gp & 4095;
        out[((size_t)b*256 + c0 + r)*4096 + p] = t[pc][r];
    }
}

// ======================= fp16 mma.sync distance =======================
// CTA: M=128 positions x N=128 codes (quarter codebook), K=256 in 8 chunks of 32.
// dot ~= Ahi*Bhi + Ahi*Blo + Alo*Bhi (products exact in fp32 accum; dropped lo*lo ~2^-22).
// 8 warps: wm=w&1 (M 64), wn=w>>1 (N 32). Warp tile 64x32, 3 x m16n8k16 per (mt,u).
#define STRH 48                         // compact: 96B stride, conflict-free compute loads
#define TILEH (128*STRH)                // 6144 halves = 12288 B per operand
#define DSMEM (4*TILEH*2 + 512)        // 49664 bytes -> 2 CTAs/SM

__global__ void __launch_bounds__(256, 2) dist_mma_kernel()
{
    extern __shared__ char smem[];
    __half* sAhi = (__half*)smem;
    __half* sAlo = sAhi + TILEH;
    __half* sBhi = sAlo + TILEH;
    __half* sBlo = sBhi + TILEH;
    float*  cbs_s = (float*)(smem + 4*TILEH*2);   // 128 floats

    int tid = threadIdx.x;
    int lane = tid & 31, w = tid >> 5;
    int g = lane >> 2, t4 = lane & 3;
    int wm = w & 1, wn = w >> 1;

    int blk = blockIdx.x;
    int seg, mtile, q;
    if (blk < 1344) { seg = 0; mtile = blk >> 2; q = blk & 3; }
    else            { seg = 1; mtile = (blk - 1344) >> 2; q = (blk - 1344) & 3; }

    const __half* Ahi_g = g_ehi + (size_t)mtile*128*256;
    const __half* Alo_g = g_elo + (size_t)mtile*128*256;
    int cbrow = (seg ? 512 : 0) + q*128;
    const __half* Bhi_g = g_cbhi + (size_t)cbrow*256;
    const __half* Blo_g = g_cblo + (size_t)cbrow*256;

    if (tid < 128) cbs_s[tid] = g_cbsq[cbrow + tid];

    float acc[4][4][4];
    #pragma unroll
    for (int mt = 0; mt < 4; mt++)
        #pragma unroll
        for (int u = 0; u < 4; u++)
            #pragma unroll
            for (int e = 0; e < 4; e++) acc[mt][u][e] = 0.f;

    const __half* gsrc[4] = {Ahi_g, Alo_g, Bhi_g, Blo_g};
    __half* sdst[4] = {sAhi, sAlo, sBhi, sBlo};

    for (int kc = 0; kc < 8; kc++) {
        if (kc > 0) __syncthreads();
        #pragma unroll
        for (int op = 0; op < 4; op++) {
            #pragma unroll
            for (int it = 0; it < 2; it++) {
                int c = it*256 + tid;
                int r = c >> 2, sgs = c & 3;
                *(uint4*)(sdst[op] + r*STRH + sgs*8) =
                    *(const uint4*)(gsrc[op] + (size_t)r*256 + kc*32 + sgs*8);
            }
        }
        __syncthreads();

        #pragma unroll
        for (int s = 0; s < 2; s++) {
            int ko = s*16 + t4*4;
            uint2 bhf[4], blf[4];
            #pragma unroll
            for (int u = 0; u < 4; u++) {
                int br = (wn*32 + u*8 + g)*STRH + ko;
                bhf[u] = *(uint2*)(sBhi + br);
                blf[u] = *(uint2*)(sBlo + br);
            }
            #pragma unroll
            for (int mt = 0; mt < 4; mt++) {
                int ar = (wm*64 + mt*16 + g)*STRH + ko;
                uint2 ah0 = *(uint2*)(sAhi + ar);
                uint2 ah1 = *(uint2*)(sAhi + ar + 8*STRH);
                uint2 al0 = *(uint2*)(sAlo + ar);
                uint2 al1 = *(uint2*)(sAlo + ar + 8*STRH);
                #pragma unroll
                for (int u = 0; u < 4; u++) {
                    mma_f16(acc[mt][u], ah0, ah1, bhf[u]);
                    mma_f16(acc[mt][u], ah0, ah1, blf[u]);
                    mma_f16(acc[mt][u], al0, al1, bhf[u]);
                }
            }
        }
    }
    __syncthreads();

    // partial overlay in smem (tiles dead now)
    float* Mp = (float*)smem;           // [128][4]
    float* Lp = Mp + 512;
    int*   Ip = (int*)(Mp + 1024);

    const float NEG = -3.402823466e38f;
    #pragma unroll
    for (int mt = 0; mt < 4; mt++) {
        #pragma unroll
        for (int half = 0; half < 2; half++) {
            int row = wm*64 + mt*16 + g + half*8;
            float M = NEG, L = 0.f; int I = 0;
            #pragma unroll
            for (int u = 0; u < 4; u++) {
                #pragma unroll
                for (int j = 0; j < 2; j++) {
                    int col = wn*32 + u*8 + 2*t4 + j;
                    float s = 2.f*acc[mt][u][half*2 + j] - cbs_s[col];
                    if (s > M) { L = L*expf(M - s) + 1.f; M = s; I = col; }
                    else       { L += expf(s - M); }
                }
            }
            #pragma unroll
            for (int off = 1; off <= 2; off <<= 1) {
                float m2 = __shfl_xor_sync(0xffffffffu, M, off);
                float l2 = __shfl_xor_sync(0xffffffffu, L, off);
                int   i2 = __shfl_xor_sync(0xffffffffu, I, off);
                float mn = fmaxf(M, m2);
                L = L*expf(M - mn) + l2*expf(m2 - mn);
                if (m2 > M || (m2 == M && i2 < I)) I = i2;
                M = mn;
            }
            if (t4 == 0) { Mp[row*4 + wn] = M; Lp[row*4 + wn] = L; Ip[row*4 + wn] = I; }
        }
    }
    __syncthreads();

    if (tid < 128) {
        float M = Mp[tid*4], L = Lp[tid*4]; int I = Ip[tid*4];
        #pragma unroll
        for (int n = 1; n < 4; n++) {
            float m2 = Mp[tid*4 + n], l2 = Lp[tid*4 + n];
            float mn = fmaxf(M, m2);
            L = L*expf(M - mn) + l2*expf(m2 - mn);
            if (m2 > M) I = Ip[tid*4 + n];   // ascending col blocks: ties keep first
            M = mn;
        }
        int pos = mtile*128 + tid;
        int slot = seg ? (172032 + q*32768 + pos) : (q*43008 + pos);
        g_hM[slot] = M; g_hL[slot] = L; g_hI[slot] = q*128 + I;
    }
}

// ======================= fuse =======================
__device__ __forceinline__ void merge4(int pos, int base, int stride, float& P, int& idx)
{
    float M = g_hM[base + pos], L = g_hL[base + pos]; int I = g_hI[base + pos];
    #pragma unroll
    for (int n = 1; n < 4; n++) {
        int s = base + n*stride + pos;
        float m2 = g_hM[s], l2 = g_hL[s];
        float mn = fmaxf(M, m2);
        L = L*expf(M - mn) + l2*expf(m2 - mn);
        if (m2 > M) I = g_hI[s];     // ascending quarters: ties keep first
        M = mn;
    }
    P = 1.f / L; idx = I;
}

__global__ void __launch_bounds__(256) fuse_kernel(
    const float* __restrict__ cbs, float* __restrict__ out)
{
    const float* cb0 = cbs;
    const float* cb1 = cbs + (size_t)KCB*CDIM;
    int x = threadIdx.x & 63;
    int y = blockIdx.x*4 + (threadIdx.x >> 6);
    int b = blockIdx.y;
    int pos0 = (b*64 + y)*64 + x;
    int pos1 = 32768 + (b*32 + (y>>1))*32 + (x>>1);
    int pos2 = 40960 + (b*16 + (y>>2))*16 + (x>>2);

    float pA, pB, pC; int zA, zB, zC;
    merge4(pos0, 0, 43008, pA, zA);
    merge4(pos1, 0, 43008, pB, zB);
    merge4(pos2, 0, 43008, pC, zC);
    int z1 = zA; float best = pA;
    if (pB > best) { best = pB; z1 = zB; }
    if (pC > best) { best = pC; z1 = zC; }
    float p2d; int z2;
    merge4(pos0, 172032, 32768, p2d, z2);

    out[OFF_Z + ((size_t)(b*2+0)*64 + y)*64 + x] = (float)z1;
    out[OFF_Z + ((size_t)(b*2+1)*64 + y)*64 + x] = (float)z2;

    const float4* r0 = (const float4*)(cb0 + (size_t)z1*CDIM);
    const float4* r1 = (const float4*)(cb1 + (size_t)z2*CDIM);
    size_t obase = (size_t)OFF_STE + (size_t)b*256*4096 + (size_t)y*64 + x;
    for (int c4 = 0; c4 < 64; c4++) {
        float4 a = r0[c4], qv = r1[c4];
        int c = c4*4;
        out[obase + (size_t)(c+0)*4096] = 0.5f*(a.x + qv.x);
        out[obase + (size_t)(c+1)*4096] = 0.5f*(a.y + qv.y);
        out[obase + (size_t)(c+2)*4096] = 0.5f*(a.z + qv.z);
        out[obase + (size_t)(c+3)*4096] = 0.5f*(a.w + qv.w);
    }
}

// ======================= launch =======================
extern "C" void kernel_launch(void* const* d_in, const int* in_sizes, int n_in,
                              void* d_out, int out_size)
{
    const float* image     = (const float*)d_in[0];  // (8,3,256,256)
    const float* conv_w    = (const float*)d_in[1];  // (256,3,4,4)
    const float* conv_b    = (const float*)d_in[2];  // (256,)
    const float* codebooks = (const float*)d_in[3];  // (4,512,256)
    float* out = (float*)d_out;

    cudaFuncSetAttribute(dist_mma_kernel, cudaFuncAttributeMaxDynamicSharedMemorySize, DSMEM);

    ds_kernel<<<1920, 256>>>(image);
    cbprep_kernel<<<1024, 256>>>(codebooks);

    conv_kernel<<<dim3(64, 8), 256>>>(image, conv_w, conv_b, 0);
    conv_kernel<<<dim3(32, 8), 256>>>(image, conv_w, conv_b, 1);
    conv_kernel<<<dim3(16, 8), 256>>>(image, conv_w, conv_b, 2);

    transpose_kernel<<<dim3(1024, 8), 256>>>(out);

    // cb0: 336 mtiles x 4 quarters = 1344 ; cb1: 256 x 4 = 1024
    dist_mma_kernel<<<2368, 256, DSMEM>>>();

    fuse_kernel<<<dim3(16, 8), 256>>>(codebooks, out);
}

// round 14
// speedup vs baseline: 1.7144x; 1.1105x over previous
#include <cuda_runtime.h>
#include <cuda_fp16.h>
#include <cstdint>

#define CDIM 256
#define KCB  512

static const int N_ENC0  = 8*256*64*64;        // 8388608
static const int OFF_Z   = N_ENC0;
static const int OFF_STE = N_ENC0 + 8*2*64*64; // + 65536

// ---- scratch (device globals; no allocation anywhere) ----
__device__ float g_img1[8*3*128*128];
__device__ float g_img2[8*3*64*64];
__device__ float g_cbsq[2*KCB];         // ||cb||^2, 1024 rows
// fp16 hi/lo split operands, k-PERMUTED within each 16-chunk:
// j=k&15 -> slot = ((j&7)>>1)*4 + ((j>>3)<<1) + (j&1)   (lane t4 owns slots 4t4..4t4+3)
__device__ __half g_ehi[43008*256];     // concat enc0|enc1|enc2 rows
__device__ __half g_elo[43008*256];
__device__ __half g_cbhi[1024*256];     // cb0 rows 0..511, cb1 rows 512..1023
__device__ __half g_cblo[1024*256];
// per-(quarter, position) partials: cb0: q*43008 + pos ; cb1: 172032 + q*32768 + pos
__device__ float g_hM[303104];
__device__ float g_hL[303104];          // only cb0 slots used
__device__ int   g_hI[303104];

// m16n8k16 fp16 MMA, fp32 accum (sm_80+ PTX)
__device__ __forceinline__ void mma_f16(float* c, uint2 a01, uint2 a23, uint2 b) {
    asm volatile("mma.sync.aligned.m16n8k16.row.col.f32.f16.f16.f32 "
        "{%0,%1,%2,%3}, {%4,%5,%6,%7}, {%8,%9}, {%0,%1,%2,%3};"
        : "+f"(c[0]), "+f"(c[1]), "+f"(c[2]), "+f"(c[3])
        : "r"(a01.x), "r"(a23.x), "r"(a01.y), "r"(a23.y),
          "r"(b.x),  "r"(b.y));
}

__device__ __forceinline__ float ex2a(float x) {
    float r; asm("ex2.approx.f32 %0, %1;" : "=f"(r) : "f"(x)); return r;
}
#define LOG2E 1.4426950408889634f

__device__ __forceinline__ int permcol(int k) {
    int j = k & 15;
    return (k & ~15) + ((j & 7) >> 1)*4 + ((j >> 3) << 1) + (j & 1);
}

// ======================= small kernels =======================
// merged bilinear downsample: blocks [0,1536) -> f=2 into g_img1; [1536,1920) -> f=4 into g_img2
__global__ void ds_kernel(const float* __restrict__ img)
{
    int sel = (blockIdx.x >= 1536);
    int base = sel ? 1536*256 : 0;
    int Wout = sel ? 64 : 128;
    int f    = sel ? 4 : 2;
    int o    = sel ? 1 : 0;
    float* out = sel ? g_img2 : g_img1;
    int idx = blockIdx.x*blockDim.x + threadIdx.x - base;
    int total = 8*3*Wout*Wout;
    if (idx >= total) return;
    int x = idx % Wout, y = (idx / Wout) % Wout, bc = idx / (Wout*Wout);
    const float* p = img + (size_t)bc*256*256;
    int ry = y*f + o, rx = x*f + o;
    out[idx] = 0.25f*(p[ry*256+rx] + p[ry*256+rx+1] + p[(ry+1)*256+rx] + p[(ry+1)*256+rx+1]);
}

// codebook: squared norms + fp16 hi/lo split (k-permuted). grid 1024, block 256.
__global__ void __launch_bounds__(256) cbprep_kernel(const float* __restrict__ cbs)
{
    __shared__ float red[8];
    int r = blockIdx.x, k = threadIdx.x;
    float v = cbs[(size_t)r*256 + k];
    __half h = __float2half_rn(v);
    __half l = __float2half_rn(v - __half2float(h));
    size_t o = (size_t)r*256 + permcol(k);
    g_cbhi[o] = h; g_cblo[o] = l;
    float s = v*v;
    #pragma unroll
    for (int off = 16; off > 0; off >>= 1) s += __shfl_xor_sync(0xffffffffu, s, off);
    if ((k & 31) == 0) red[k >> 5] = s;
    __syncthreads();
    if (k == 0) {
        float t = 0.f;
        #pragma unroll
        for (int i = 0; i < 8; i++) t += red[i];
        g_cbsq[r] = t;
    }
}

// stride-4 4x4 conv, 3 in-ch -> 256 out-ch; writes fp16 split.
// which==0 additionally writes the NCHW fp32 output (region 0) via smem-staged transpose.
// grid: (Hout, B); block: 256 threads (one per out channel).
__global__ void __launch_bounds__(256) conv_kernel(
    const float* __restrict__ ext_img, const float* __restrict__ w,
    const float* __restrict__ bias, float* __restrict__ out, int which)
{
    __shared__ __align__(16) float ins[12][256];
    __shared__ float stage[256][17];    // conv0 NCHW staging (17: conflict-free both phases)
    int o = threadIdx.x;
    int y = blockIdx.x, b = blockIdx.y;
    int Hout = gridDim.x;
    int Win  = Hout * 4;

    const float* img = (which == 0) ? ext_img : (which == 1 ? g_img1 : g_img2);
    int rowbase = (which == 0) ? (b*64 + y)*64
                : (which == 1) ? 32768 + (b*32 + y)*32
                               : 40960 + (b*16 + y)*16;

    int tot = 12*Win;
    for (int i = o; i < tot; i += 256) {
        int x = i % Win; int r = i / Win;      // r = ic*4 + ky
        ins[r][x] = img[(((size_t)b*3 + (r>>2))*Win + 4*y + (r&3))*Win + x];
    }
    float wreg[48];
    #pragma unroll
    for (int j = 0; j < 48; j++) wreg[j] = w[(size_t)o*48 + j];
    float bo = bias[o];
    __syncthreads();

    int oc = permcol(o);
    if (which == 0) {
        for (int xc = 0; xc < 64; xc += 16) {
            for (int x2 = 0; x2 < 16; x2 += 2) {
                int x = xc + x2;
                float aA = bo, aB = bo;
                #pragma unroll
                for (int r = 0; r < 12; r++) {
                    float4 vA = *(const float4*)&ins[r][4*x];
                    float4 vB = *(const float4*)&ins[r][4*x + 4];
                    aA += wreg[r*4+0]*vA.x; aB += wreg[r*4+0]*vB.x;
                    aA += wreg[r*4+1]*vA.y; aB += wreg[r*4+1]*vB.y;
                    aA += wreg[r*4+2]*vA.z; aB += wreg[r*4+2]*vB.z;
                    aA += wreg[r*4+3]*vA.w; aB += wreg[r*4+3]*vB.w;
                }
                size_t pA = (size_t)rowbase + x, pB = pA + 1;
                __half hA = __float2half_rn(aA);
                __half lA = __float2half_rn(aA - __half2float(hA));
                __half hB = __float2half_rn(aB);
                __half lB = __float2half_rn(aB - __half2float(hB));
                g_ehi[pA*256 + oc] = hA; g_elo[pA*256 + oc] = lA;
                g_ehi[pB*256 + oc] = hB; g_elo[pB*256 + oc] = lB;
                stage[o][x2] = aA; stage[o][x2+1] = aB;
            }
            __syncthreads();
            int xx = o & 15, cg = o >> 4;
            #pragma unroll
            for (int c0 = 0; c0 < 16; c0++) {
                int c = c0*16 + cg;
                out[((size_t)(b*256 + c)*64 + y)*64 + xc + xx] = stage[c][xx];
            }
            __syncthreads();
        }
    } else {
        for (int x = 0; x < Hout; x += 2) {
            float aA = bo, aB = bo;
            #pragma unroll
            for (int r = 0; r < 12; r++) {
                float4 vA = *(const float4*)&ins[r][4*x];
                float4 vB = *(const float4*)&ins[r][4*x + 4];
                aA += wreg[r*4+0]*vA.x; aB += wreg[r*4+0]*vB.x;
                aA += wreg[r*4+1]*vA.y; aB += wreg[r*4+1]*vB.y;
                aA += wreg[r*4+2]*vA.z; aB += wreg[r*4+2]*vB.z;
                aA += wreg[r*4+3]*vA.w; aB += wreg[r*4+3]*vB.w;
            }
            size_t pA = (size_t)rowbase + x, pB = pA + 1;
            __half hA = __float2half_rn(aA);
            __half lA = __float2half_rn(aA - __half2float(hA));
            __half hB = __float2half_rn(aB);
            __half lB = __float2half_rn(aB - __half2float(hB));
            g_ehi[pA*256 + oc] = hA; g_elo[pA*256 + oc] = lA;
            g_ehi[pB*256 + oc] = hB; g_elo[pB*256 + oc] = lB;
        }
    }
}

// ======================= fp16 mma.sync distance =======================
// CTA: M=128 positions x N=128 codes (quarter codebook), K=256 in 8 chunks of 32.
// dot ~= Ahi*Bhi + Ahi*Blo + Alo*Bhi (products exact in fp32 accum; dropped lo*lo ~2^-22).
// 8 warps: wm=w&1 (M 64), wn=w>>1 (N 32). Warp tile 64x32, 3 x m16n8k16 per (mt,u).
// Epilogue: two-pass (max/argmax, then sum ex2). cb1 (seg==1) skips L entirely.
#define STRH 48                         // compact: 96B stride, conflict-free compute loads
#define TILEH (128*STRH)                // 6144 halves = 12288 B per operand
#define DSMEM (4*TILEH*2 + 512)        // 49664 bytes -> 2 CTAs/SM

__global__ void __launch_bounds__(256, 2) dist_mma_kernel()
{
    extern __shared__ char smem[];
    __half* sAhi = (__half*)smem;
    __half* sAlo = sAhi + TILEH;
    __half* sBhi = sAlo + TILEH;
    __half* sBlo = sBhi + TILEH;
    float*  cbs_s = (float*)(smem + 4*TILEH*2);   // 128 floats

    int tid = threadIdx.x;
    int lane = tid & 31, w = tid >> 5;
    int g = lane >> 2, t4 = lane & 3;
    int wm = w & 1, wn = w >> 1;

    int blk = blockIdx.x;
    int seg, mtile, q;
    if (blk < 1344) { seg = 0; mtile = blk >> 2; q = blk & 3; }
    else            { seg = 1; mtile = (blk - 1344) >> 2; q = (blk - 1344) & 3; }

    const __half* Ahi_g = g_ehi + (size_t)mtile*128*256;
    const __half* Alo_g = g_elo + (size_t)mtile*128*256;
    int cbrow = (seg ? 512 : 0) + q*128;
    const __half* Bhi_g = g_cbhi + (size_t)cbrow*256;
    const __half* Blo_g = g_cblo + (size_t)cbrow*256;

    if (tid < 128) cbs_s[tid] = g_cbsq[cbrow + tid];

    float acc[4][4][4];
    #pragma unroll
    for (int mt = 0; mt < 4; mt++)
        #pragma unroll
        for (int u = 0; u < 4; u++)
            #pragma unroll
            for (int e = 0; e < 4; e++) acc[mt][u][e] = 0.f;

    const __half* gsrc[4] = {Ahi_g, Alo_g, Bhi_g, Blo_g};
    __half* sdst[4] = {sAhi, sAlo, sBhi, sBlo};

    for (int kc = 0; kc < 8; kc++) {
        if (kc > 0) __syncthreads();
        #pragma unroll
        for (int op = 0; op < 4; op++) {
            #pragma unroll
            for (int it = 0; it < 2; it++) {
                int c = it*256 + tid;
                int r = c >> 2, sgs = c & 3;
                *(uint4*)(sdst[op] + r*STRH + sgs*8) =
                    *(const uint4*)(gsrc[op] + (size_t)r*256 + kc*32 + sgs*8);
            }
        }
        __syncthreads();

        #pragma unroll
        for (int s = 0; s < 2; s++) {
            int ko = s*16 + t4*4;
            uint2 bhf[4], blf[4];
            #pragma unroll
            for (int u = 0; u < 4; u++) {
                int br = (wn*32 + u*8 + g)*STRH + ko;
                bhf[u] = *(uint2*)(sBhi + br);
                blf[u] = *(uint2*)(sBlo + br);
            }
            #pragma unroll
            for (int mt = 0; mt < 4; mt++) {
                int ar = (wm*64 + mt*16 + g)*STRH + ko;
                uint2 ah0 = *(uint2*)(sAhi + ar);
                uint2 ah1 = *(uint2*)(sAhi + ar + 8*STRH);
                uint2 al0 = *(uint2*)(sAlo + ar);
                uint2 al1 = *(uint2*)(sAlo + ar + 8*STRH);
                #pragma unroll
                for (int u = 0; u < 4; u++) {
                    mma_f16(acc[mt][u], ah0, ah1, bhf[u]);
                    mma_f16(acc[mt][u], ah0, ah1, blf[u]);
                    mma_f16(acc[mt][u], al0, al1, bhf[u]);
                }
            }
        }
    }
    __syncthreads();

    // partial overlay in smem (tiles dead now)
    float* Mp = (float*)smem;           // [128][4]
    float* Lp = Mp + 512;
    int*   Ip = (int*)(Mp + 1024);

    const float NEG = -3.402823466e38f;
    #pragma unroll
    for (int mt = 0; mt < 4; mt++) {
        #pragma unroll
        for (int half = 0; half < 2; half++) {
            int row = wm*64 + mt*16 + g + half*8;
            // pass 0: s values
            float sv[8];
            #pragma unroll
            for (int u = 0; u < 4; u++)
                #pragma unroll
                for (int j = 0; j < 2; j++) {
                    int col = wn*32 + u*8 + 2*t4 + j;
                    sv[u*2 + j] = 2.f*acc[mt][u][half*2 + j] - cbs_s[col];
                }
            // pass 1: max/argmax (cols ascending per thread -> '>' keeps first)
            float M = NEG; int I = 0;
            #pragma unroll
            for (int t = 0; t < 8; t++) {
                int col = wn*32 + (t >> 1)*8 + 2*t4 + (t & 1);
                if (sv[t] > M) { M = sv[t]; I = col; }
            }
            #pragma unroll
            for (int off = 1; off <= 2; off <<= 1) {
                float m2 = __shfl_xor_sync(0xffffffffu, M, off);
                int   i2 = __shfl_xor_sync(0xffffffffu, I, off);
                if (m2 > M || (m2 == M && i2 < I)) I = i2;
                M = fmaxf(M, m2);
            }
            // pass 2 (cb0 only): L = sum ex2((s - M)*log2e)
            float L = 0.f;
            if (seg == 0) {
                float ls = 0.f;
                #pragma unroll
                for (int t = 0; t < 8; t++) ls += ex2a((sv[t] - M)*LOG2E);
                #pragma unroll
                for (int off = 1; off <= 2; off <<= 1)
                    ls += __shfl_xor_sync(0xffffffffu, ls, off);
                L = ls;
            }
            if (t4 == 0) { Mp[row*4 + wn] = M; Lp[row*4 + wn] = L; Ip[row*4 + wn] = I; }
        }
    }
    __syncthreads();

    if (tid < 128) {
        float M = Mp[tid*4], L = Lp[tid*4]; int I = Ip[tid*4];
        #pragma unroll
        for (int n = 1; n < 4; n++) {
            float m2 = Mp[tid*4 + n];
            float mn = fmaxf(M, m2);
            L = L*ex2a((M - mn)*LOG2E) + Lp[tid*4 + n]*ex2a((m2 - mn)*LOG2E);
            if (m2 > M) I = Ip[tid*4 + n];   // ascending col blocks: ties keep first
            M = mn;
        }
        int pos = mtile*128 + tid;
        int slot = seg ? (172032 + q*32768 + pos) : (q*43008 + pos);
        g_hM[slot] = M; g_hI[slot] = q*128 + I;
        if (seg == 0) g_hL[slot] = L;
    }
}

// ======================= fuse =======================
__device__ __forceinline__ void merge4(int pos, int base, int stride, float& P, int& idx)
{
    float M = g_hM[base + pos], L = g_hL[base + pos]; int I = g_hI[base + pos];
    #pragma unroll
    for (int n = 1; n < 4; n++) {
        int s = base + n*stride + pos;
        float m2 = g_hM[s], l2 = g_hL[s];
        float mn = fmaxf(M, m2);
        L = L*ex2a((M - mn)*LOG2E) + l2*ex2a((m2 - mn)*LOG2E);
        if (m2 > M) I = g_hI[s];     // ascending quarters: ties keep first
        M = mn;
    }
    P = 1.f / L; idx = I;
}

__device__ __forceinline__ int merge4max(int pos, int base, int stride)
{
    float M = g_hM[base + pos]; int I = g_hI[base + pos];
    #pragma unroll
    for (int n = 1; n < 4; n++) {
        int s = base + n*stride + pos;
        float m2 = g_hM[s];
        if (m2 > M) { M = m2; I = g_hI[s]; }
    }
    return I;
}

__global__ void __launch_bounds__(256) fuse_kernel(
    const float* __restrict__ cbs, float* __restrict__ out)
{
    const float* cb0 = cbs;
    const float* cb1 = cbs + (size_t)KCB*CDIM;
    int x = threadIdx.x & 63;
    int y = blockIdx.x*4 + (threadIdx.x >> 6);
    int b = blockIdx.y;
    int pos0 = (b*64 + y)*64 + x;
    int pos1 = 32768 + (b*32 + (y>>1))*32 + (x>>1);
    int pos2 = 40960 + (b*16 + (y>>2))*16 + (x>>2);

    float pA, pB, pC; int zA, zB, zC;
    merge4(pos0, 0, 43008, pA, zA);
    merge4(pos1, 0, 43008, pB, zB);
    merge4(pos2, 0, 43008, pC, zC);
    int z1 = zA; float best = pA;
    if (pB > best) { best = pB; z1 = zB; }
    if (pC > best) { best = pC; z1 = zC; }
    int z2 = merge4max(pos0, 172032, 32768);

    out[OFF_Z + ((size_t)(b*2+0)*64 + y)*64 + x] = (float)z1;
    out[OFF_Z + ((size_t)(b*2+1)*64 + y)*64 + x] = (float)z2;

    const float4* r0 = (const float4*)(cb0 + (size_t)z1*CDIM);
    const float4* r1 = (const float4*)(cb1 + (size_t)z2*CDIM);
    size_t obase = (size_t)OFF_STE + (size_t)b*256*4096 + (size_t)y*64 + x;
    for (int c4 = 0; c4 < 64; c4++) {
        float4 a = r0[c4], qv = r1[c4];
        int c = c4*4;
        out[obase + (size_t)(c+0)*4096] = 0.5f*(a.x + qv.x);
        out[obase + (size_t)(c+1)*4096] = 0.5f*(a.y + qv.y);
        out[obase + (size_t)(c+2)*4096] = 0.5f*(a.z + qv.z);
        out[obase + (size_t)(c+3)*4096] = 0.5f*(a.w + qv.w);
    }
}

// ======================= launch =======================
extern "C" void kernel_launch(void* const* d_in, const int* in_sizes, int n_in,
                              void* d_out, int out_size)
{
    const float* image     = (const float*)d_in[0];  // (8,3,256,256)
    const float* conv_w    = (const float*)d_in[1];  // (256,3,4,4)
    const float* conv_b    = (const float*)d_in[2];  // (256,)
    const float* codebooks = (const float*)d_in[3];  // (4,512,256)
    float* out = (float*)d_out;

    cudaFuncSetAttribute(dist_mma_kernel, cudaFuncAttributeMaxDynamicSharedMemorySize, DSMEM);

    ds_kernel<<<1920, 256>>>(image);
    cbprep_kernel<<<1024, 256>>>(codebooks);

    conv_kernel<<<dim3(64, 8), 256>>>(image, conv_w, conv_b, out, 0);
    conv_kernel<<<dim3(32, 8), 256>>>(image, conv_w, conv_b, out, 1);
    conv_kernel<<<dim3(16, 8), 256>>>(image, conv_w, conv_b, out, 2);

    // cb0: 336 mtiles x 4 quarters = 1344 ; cb1: 256 x 4 = 1024
    dist_mma_kernel<<<2368, 256, DSMEM>>>();

    fuse_kernel<<<dim3(16, 8), 256>>>(codebooks, out);
}